// round 15
// baseline (speedup 1.0000x reference)
#include <cuda_runtime.h>
#include <cstdint>

// Problem constants
#define B_   4
#define C_   128
#define H_   192
#define W_   192
#define HW_  (H_*W_)
#define K_   9
#define PAD  4
#define NOFF 81

// Tiling: occ-3, CH=8, 4-deep cp.async pipeline
#define TH   8
#define TW   16
#define PXT  4
#define NTHREADS 288           // 4 wg * 9 io * 8 hr
#define CH   8
#define NSTAGE 16
#define NBUF 4
#define YROWS 16               // TH + 2*PAD
#define YPITCH 48              // ≡16 mod 32 -> conflict-free; 2 channels share one row
#define XPITCH 16
#define XSZ  (CH*TH*XPITCH)    // 1024 floats
#define YSZ  (4*YROWS*YPITCH)  // 3072 floats (4 rowsets x 2 col-halves)
#define BUFSZ (XSZ + YSZ)      // 4096 floats = 16KB/stage
#define SMEM_BYTES (NBUF*BUFSZ*4) // 65536 bytes  (3 blocks x 64KB = 192KB <= 228KB)

typedef unsigned long long u64;

__device__ __forceinline__ u64 pack2(float lo, float hi) {
    u64 r;
    asm("mov.b64 %0, {%1, %2};" : "=l"(r) : "f"(lo), "f"(hi));
    return r;
}
__device__ __forceinline__ u64 ffma2u(u64 a, u64 b, u64 c) {
    u64 d;
    asm("fma.rn.f32x2 %0, %1, %2, %3;" : "=l"(d) : "l"(a), "l"(b), "l"(c));
    return d;
}
__device__ __forceinline__ float2 unpack2(u64 v) {
    float2 r;
    asm("mov.b64 {%0, %1}, %2;" : "=f"(r.x), "=f"(r.y) : "l"(v));
    return r;
}

__device__ __forceinline__ void cp16(uint32_t dst, const void* src, int srcsize) {
    asm volatile("cp.async.cg.shared.global [%0], [%1], 16, %2;"
                 :: "r"(dst), "l"(src), "r"(srcsize));
}
__device__ __forceinline__ void cp_commit() {
    asm volatile("cp.async.commit_group;");
}
template <int N>
__device__ __forceinline__ void cp_wait() {
    asm volatile("cp.async.wait_group %0;" :: "n"(N));
}

__global__ void __launch_bounds__(NTHREADS, 3)
corr_kernel(const float* __restrict__ x,
            const float* __restrict__ y,
            float* __restrict__ out) {
    extern __shared__ float sm[];

    const int tid = threadIdx.x;
    const int wg  = tid & 3;
    const int io  = (tid >> 2) % 9;
    const int hr  = tid / 36;

    const int b  = blockIdx.z;
    const int h0 = blockIdx.y * TH;
    const int w0 = blockIdx.x * TW;

    const float* xb = x + (size_t)b * C_ * HW_;
    const float* yb = y + (size_t)b * C_ * HW_;

    const uint32_t sm_base = (uint32_t)__cvta_generic_to_shared(sm);

    // y chunk 0..767 -> channel c (0..7): rowset (c&3), col-half (c>>2)
    auto y_chunk = [&](int c0, uint32_t ys_base, int chunk) {
        int t = chunk / 6;
        int q = chunk - 6 * t;
        int c = t >> 4;               // 0..7
        int r = t & 15;
        int gh = h0 + r - PAD;
        int gw = w0 - 4 + q * 4;
        bool ok = ((unsigned)gh < (unsigned)H_) &&
                  ((unsigned)gw <= (unsigned)(W_ - 4));
        const float* src = ok ? yb + (size_t)(c0 + c) * HW_ + gh * W_ + gw : yb;
        uint32_t dst = ys_base +
            (uint32_t)(((c & 3) * YROWS + r) * YPITCH + (c >> 2) * 24 + q * 4) * 4u;
        cp16(dst, src, ok ? 16 : 0);
    };

    // one stage: x 256 f4 + y 768 f4, 4 cp per thread (tid < 256)
    auto prefetch = [&](int s, int buf) {
        const int c0 = s * CH;
        const uint32_t base = sm_base + (uint32_t)(buf * BUFSZ) * 4u;
        if (tid < 256) {
            int c  = tid >> 5;        // 0..7
            int r  = (tid >> 2) & 7;
            int c4 = tid & 3;
            const float* src = xb + (size_t)(c0 + c) * HW_ + (h0 + r) * W_ + w0 + c4 * 4;
            cp16(base + (uint32_t)((c * TH + r) * XPITCH + c4 * 4) * 4u, src, 16);
            const uint32_t ysb = base + (uint32_t)XSZ * 4u;
            y_chunk(c0, ysb, tid);
            y_chunk(c0, ysb, tid + 256);
            y_chunk(c0, ysb, tid + 512);
        }
        cp_commit();
    };

    // accumulators: acc[j][q], pixel pair (2q, 2q+1); 18 u64 = 36 regs
    u64 acc[K_][2];
#pragma unroll
    for (int j = 0; j < K_; j++) { acc[j][0] = 0ull; acc[j][1] = 0ull; }

    // 4 channels of one col-half
    auto compute_half = [&](int buf, int half) {
        const float* xp = sm + buf * BUFSZ + (half * 4 * TH + hr) * XPITCH + wg * PXT;
        const float* yr = sm + buf * BUFSZ + XSZ + (hr + io) * YPITCH
                          + half * 24 + wg * PXT;
#pragma unroll
        for (int c = 0; c < 4; c++) {
            const float* xc = xp + c * (TH * XPITCH);
            const float* yc = yr + c * (YROWS * YPITCH);

            float4 xa = *(const float4*)xc;
            u64 xe0 = pack2(xa.x, xa.y);
            u64 xe1 = pack2(xa.z, xa.w);

            float4 y0 = *(const float4*)(yc);
            u64 e0 = pack2(y0.x, y0.y);
            u64 e1 = pack2(y0.z, y0.w);
            u64 o0 = pack2(y0.y, y0.z);
            acc[0][0] = ffma2u(xe0, e0, acc[0][0]);
            acc[2][0] = ffma2u(xe0, e1, acc[2][0]);
            acc[0][1] = ffma2u(xe1, e1, acc[0][1]);
            acc[1][0] = ffma2u(xe0, o0, acc[1][0]);

            float4 y1 = *(const float4*)(yc + 4);
            u64 o1 = pack2(y0.w, y1.x);
            u64 e2 = pack2(y1.x, y1.y);
            u64 e3 = pack2(y1.z, y1.w);
            u64 o2 = pack2(y1.y, y1.z);
            acc[3][0] = ffma2u(xe0, o1, acc[3][0]);
            acc[1][1] = ffma2u(xe1, o1, acc[1][1]);
            acc[4][0] = ffma2u(xe0, e2, acc[4][0]);
            acc[2][1] = ffma2u(xe1, e2, acc[2][1]);
            acc[6][0] = ffma2u(xe0, e3, acc[6][0]);
            acc[4][1] = ffma2u(xe1, e3, acc[4][1]);
            acc[5][0] = ffma2u(xe0, o2, acc[5][0]);
            acc[3][1] = ffma2u(xe1, o2, acc[3][1]);

            float4 y2 = *(const float4*)(yc + 8);
            u64 o3 = pack2(y1.w, y2.x);
            u64 e4 = pack2(y2.x, y2.y);
            u64 e5 = pack2(y2.z, y2.w);
            u64 o4 = pack2(y2.y, y2.z);
            acc[7][0] = ffma2u(xe0, o3, acc[7][0]);
            acc[5][1] = ffma2u(xe1, o3, acc[5][1]);
            acc[8][0] = ffma2u(xe0, e4, acc[8][0]);
            acc[6][1] = ffma2u(xe1, e4, acc[6][1]);
            acc[8][1] = ffma2u(xe1, e5, acc[8][1]);
            acc[7][1] = ffma2u(xe1, o4, acc[7][1]);
        }
    };

    // fill pipeline 3 deep
    prefetch(0, 0);
    prefetch(1, 1);
    prefetch(2, 2);

    for (int s = 0; s < NSTAGE; s++) {
        // ensure stage-s group complete (issued 3 stages ago except at tail)
        if (s <= NSTAGE - 3)      cp_wait<2>();
        else if (s == NSTAGE - 2) cp_wait<1>();
        else                      cp_wait<0>();
        __syncthreads();          // publish stage s; buf (s+3)&3 == (s-1)&3 free
        if (s + 3 < NSTAGE) prefetch(s + 3, (s + 3) & 3);

        const int buf = s & 3;
        compute_half(buf, 0);
        compute_half(buf, 1);
    }

    // ---- epilogue: 9 float4 stores ----
    const float inv_c = 1.0f / (float)C_;
    const int hrow = h0 + hr;
#pragma unroll
    for (int j = 0; j < K_; j++) {
        int o = io * K_ + j;
        float* op = out + (((size_t)b * NOFF + o) * H_ + hrow) * W_ + w0 + wg * PXT;
        float2 v0 = unpack2(acc[j][0]);
        float2 v1 = unpack2(acc[j][1]);
        *(float4*)op = make_float4(v0.x * inv_c, v0.y * inv_c,
                                   v1.x * inv_c, v1.y * inv_c);
    }
}

extern "C" void kernel_launch(void* const* d_in, const int* in_sizes, int n_in,
                              void* d_out, int out_size) {
    const float* x = (const float*)d_in[0];
    const float* y = (const float*)d_in[1];
    float* out = (float*)d_out;

    static bool attr_set = false;
    if (!attr_set) {
        cudaFuncSetAttribute(corr_kernel,
                             cudaFuncAttributeMaxDynamicSharedMemorySize,
                             SMEM_BYTES);
        attr_set = true;
    }

    dim3 grid(W_ / TW, H_ / TH, B_);   // 12 x 24 x 4 = 1152 blocks
    corr_kernel<<<grid, NTHREADS, SMEM_BYTES>>>(x, y, out);
}